// round 5
// baseline (speedup 1.0000x reference)
#include <cuda_runtime.h>
#include <math.h>

// Problem constants
#define BB 8
#define TT 2048
#define DIN 256
#define HH 512
#define NCTA 128
#define L0N 64

typedef unsigned long long u64;

// ---------------- device scratch (static globals: allocation-free) ----------------
__device__ float g_h1buf[TT + 1][HH * BB];   // 33.6MB: full h1 history, [j*8+b]
__device__ float g_h2[2][HH * BB];           // ping-pong h2
__device__ unsigned g_l0f[64];               // layer0 per-CTA progress flags
__device__ unsigned g_l1f[64];               // layer1 per-CTA progress flags

// ---------------- shared memory layout (floats) ----------------
// wS   : [K][36]   K = 768 (L0: U0|W0) or 1024 (L1: W1|U1)   max 36864
// hS   : [1024][8]                                            8192
// xS   : [256][10] (L0 only)                                  2560
// redS : [64][34]                                             2176
#define OFF_H   36864
#define OFF_X   45056
#define OFF_RED 47616
#define SMEM_FLOATS 49792
#define SMEM_BYTES (SMEM_FLOATS * 4)   // 199168 < 227KB

__device__ __forceinline__ u64 pk2(float x) {
    u64 r; asm("mov.b64 %0, {%1, %1};" : "=l"(r) : "f"(x)); return r;
}
__device__ __forceinline__ void fma2(u64& a, u64 b, u64 c) {
    asm("fma.rn.f32x2 %0, %1, %2, %0;" : "+l"(a) : "l"(b), "l"(c));
}
__device__ __forceinline__ u64 addp(u64 a, u64 b) {
    u64 r; asm("add.rn.f32x2 %0, %1, %2;" : "=l"(r) : "l"(a), "l"(b)); return r;
}
__device__ __forceinline__ float4 ldcg4(const float4* p) { return __ldcg(p); }
__device__ __forceinline__ unsigned ldacq(const unsigned* p) {
    unsigned v;
    asm volatile("ld.acquire.gpu.global.u32 %0, [%1];" : "=r"(v) : "l"(p) : "memory");
    return v;
}
__device__ __forceinline__ void strel(unsigned* p, unsigned v) {
    asm volatile("st.release.gpu.global.u32 [%0], %1;" :: "l"(p), "r"(v) : "memory");
}

// wait until all 64 flags >= tgt (call with t<32 only, then __syncthreads outside)
__device__ __forceinline__ void poll64(const unsigned* f, unsigned tgt, int lane) {
    for (;;) {
        unsigned a = ldacq(f + lane);
        unsigned b = ldacq(f + 32 + lane);
        if (__all_sync(0xffffffffu, (a >= tgt) && (b >= tgt))) return;
    }
}

// acc[row*4+pair] += w.{x,y,z,w} * hpair
#define FMA16(W, H0, H1, H2, H3)                                        \
    { u64 wp;                                                           \
      wp = pk2(W.x); fma2(acc[0],wp,H0);  fma2(acc[1],wp,H1);           \
                     fma2(acc[2],wp,H2);  fma2(acc[3],wp,H3);           \
      wp = pk2(W.y); fma2(acc[4],wp,H0);  fma2(acc[5],wp,H1);           \
                     fma2(acc[6],wp,H2);  fma2(acc[7],wp,H3);           \
      wp = pk2(W.z); fma2(acc[8],wp,H0);  fma2(acc[9],wp,H1);           \
                     fma2(acc[10],wp,H2); fma2(acc[11],wp,H3);          \
      wp = pk2(W.w); fma2(acc[12],wp,H0); fma2(acc[13],wp,H1);          \
                     fma2(acc[14],wp,H2); fma2(acc[15],wp,H3); }

__global__ void init_k() {
    int t = threadIdx.x;
    for (int i = t; i < HH * BB; i += 256) g_h1buf[0][i] = 0.f;
    float* h2f = (float*)g_h2;
    for (int i = t; i < 2 * HH * BB; i += 256) h2f[i] = 0.f;
    if (t < 64) { g_l0f[t] = 0u; g_l1f[t] = 0u; }
}

__global__ void __launch_bounds__(256, 1)
lstm_persist(const float* __restrict__ x,
             const float* __restrict__ w0w, const float* __restrict__ w0b,
             const float* __restrict__ u0w, const float* __restrict__ u0b,
             const float* __restrict__ w1w, const float* __restrict__ w1b,
             const float* __restrict__ u1w, const float* __restrict__ u1b,
             float* __restrict__ out)
{
    extern __shared__ float sm[];
    float* wS   = sm;
    float* hS   = sm + OFF_H;
    float* xS   = sm + OFF_X;
    float* redS = sm + OFF_RED;

    const int t   = threadIdx.x;
    const int cta = blockIdx.x;
    const int jg  = t & 7;      // j-group (4 rows each)
    const int kg  = t >> 3;     // k-group 0..31
    const int uu  = t >> 3;     // update: unit (valid t<64)
    const int ub  = t & 7;      // update: batch
    const float4* w4 = (const float4*)wS;

    if (cta < L0N) {
        // ================= LAYER 0 =================
        const int ubase = cta * 8;
        for (int rr = 0; rr < 32; ++rr) {
            int g = (rr >> 3) * 512 + ubase + (rr & 7);
            for (int k = t; k < 768; k += 256)
                wS[k * 36 + rr] = (k < 512) ? u0w[g * 512 + k]
                                            : w0w[g * 256 + (k - 512)];
        }
        float biasv[4];
        if (t < 64) {
            #pragma unroll
            for (int g = 0; g < 4; ++g) {
                int gi = g * 512 + ubase + uu;
                biasv[g] = w0b[gi] + u0b[gi];
            }
        }
        __syncthreads();

        // x slice prefetch registers (b = t&7, d4 = t>>3 and +32)
        const int xb = t & 7, xd = t >> 3;
        const float* xrow = &x[(size_t)xb * TT * DIN];
        float4 xr0 = *(const float4*)&xrow[0 * DIN + xd * 4];
        float4 xr1 = *(const float4*)&xrow[0 * DIN + (xd + 32) * 4];

        float c_state = 0.f;
        for (int r = 0; r < TT; ++r) {
            // stage x[r] slice -> xS[d][b] (pad 10), conflict-free
            {
                float* p0 = &xS[(xd * 4) * 10 + xb];
                p0[0] = xr0.x; p0[10] = xr0.y; p0[20] = xr0.z; p0[30] = xr0.w;
                float* p1 = &xS[((xd + 32) * 4) * 10 + xb];
                p1[0] = xr1.x; p1[10] = xr1.y; p1[20] = xr1.z; p1[30] = xr1.w;
            }
            if (r + 1 < TT) {
                xr0 = *(const float4*)&xrow[(r + 1) * DIN + xd * 4];
                xr1 = *(const float4*)&xrow[(r + 1) * DIN + (xd + 32) * 4];
            }
            __syncthreads();

            u64 acc[16];
            #pragma unroll
            for (int i = 0; i < 16; ++i) acc[i] = 0ull;

            // phase A: W0 * x[r]  (pre-barrier, hides flag propagation)
            #pragma unroll
            for (int kk = 0; kk < 8; ++kk) {
                const int kx = kg * 8 + kk;
                float4 w = w4[(512 + kx) * 9 + jg];
                const u64* xp = (const u64*)(xS + kx * 10);
                u64 h0 = xp[0], h1 = xp[1], h2v = xp[2], h3 = xp[3];
                FMA16(w, h0, h1, h2v, h3)
            }

            // wait for group: h1buf[r] ready
            if (t < 32) poll64(g_l0f, (unsigned)r, t);
            __syncthreads();

            // stage h1buf[r] -> hS[0..511][8]
            {
                const float4* s = (const float4*)g_h1buf[r];
                float4* d = (float4*)hS;
                #pragma unroll
                for (int i = 0; i < 4; ++i) d[t + i * 256] = ldcg4(s + t + i * 256);
            }
            __syncthreads();

            // phase B: U0 * h1[r]
            #pragma unroll
            for (int kk = 0; kk < 16; ++kk) {
                const int k = kg * 16 + kk;
                float4 w = w4[k * 9 + jg];
                const u64* hp = (const u64*)(hS + k * 8);
                u64 h0 = hp[0], h1 = hp[1], h2v = hp[2], h3 = hp[3];
                FMA16(w, h0, h1, h2v, h3)
            }

            // in-warp reduction over 4 k-subgroups
            #pragma unroll
            for (int i = 0; i < 16; ++i) {
                acc[i] = addp(acc[i], __shfl_xor_sync(0xffffffffu, acc[i], 8));
                acc[i] = addp(acc[i], __shfl_xor_sync(0xffffffffu, acc[i], 16));
            }
            if ((t & 24) == 0) {
                u64* rb = (u64*)(redS + ((t >> 5) * 8 + jg) * 34);
                #pragma unroll
                for (int i = 0; i < 16; ++i) rb[i] = acc[i];
            }
            __syncthreads();

            if (t < 64) {
                float s4[4];
                #pragma unroll
                for (int g = 0; g < 4; ++g) {
                    const int row = g * 8 + uu;
                    const int jgg = row >> 2, rrg = row & 3;
                    float s = biasv[g];
                    #pragma unroll
                    for (int k2 = 0; k2 < 8; ++k2)
                        s += redS[(k2 * 8 + jgg) * 34 + rrg * 8 + ub];
                    s4[g] = s;
                }
                float si = __fdividef(1.f, 1.f + __expf(-s4[0]));
                float sf = __fdividef(1.f, 1.f + __expf(-s4[1]));
                float tg = tanhf(s4[2]);
                float so = __fdividef(1.f, 1.f + __expf(-s4[3]));
                c_state = sf * c_state + si * tg;
                float h = so * fmaxf(c_state, 0.f);
                const int j = ubase + uu;
                __stcg(&g_h1buf[r + 1][j * 8 + ub], h);
                if (r == TT - 1) {
                    out[8388608 + ub * 512 + j] = h;        // hh[0]
                    out[8396800 + ub * 512 + j] = c_state;  // cc[0]
                }
            }
            __syncthreads();
            if (t == 0) strel(&g_l0f[cta], (unsigned)(r + 1));
        }
    } else {
        // ================= LAYER 1 =================
        const int lcta = cta - L0N;
        const int ubase = lcta * 8;
        for (int rr = 0; rr < 32; ++rr) {
            int g = (rr >> 3) * 512 + ubase + (rr & 7);
            for (int k = t; k < 1024; k += 256)
                wS[k * 36 + rr] = (k < 512) ? w1w[g * 512 + k]
                                            : u1w[g * 512 + (k - 512)];
        }
        float biasv[4];
        if (t < 64) {
            #pragma unroll
            for (int g = 0; g < 4; ++g) {
                int gi = g * 512 + ubase + uu;
                biasv[g] = w1b[gi] + u1b[gi];
            }
        }
        __syncthreads();

        float c_state = 0.f;
        for (int r = 0; r < TT; ++r) {
            // wait for layer0: h1[r] = h1buf[r+1]
            if (t < 32) poll64(g_l0f, (unsigned)(r + 1), t);
            __syncthreads();
            {
                const float4* s = (const float4*)g_h1buf[r + 1];
                float4* d = (float4*)hS;
                #pragma unroll
                for (int i = 0; i < 4; ++i) d[t + i * 256] = ldcg4(s + t + i * 256);
            }
            __syncthreads();

            u64 acc[16];
            #pragma unroll
            for (int i = 0; i < 16; ++i) acc[i] = 0ull;

            // phase A: W1 * h1[r]  (pre-barrier)
            #pragma unroll
            for (int kk = 0; kk < 16; ++kk) {
                const int k = kg * 16 + kk;
                float4 w = w4[k * 9 + jg];
                const u64* hp = (const u64*)(hS + k * 8);
                u64 h0 = hp[0], h1 = hp[1], h2v = hp[2], h3 = hp[3];
                FMA16(w, h0, h1, h2v, h3)
            }

            // wait for own group: h2[r-1] ready
            if (t < 32) poll64(g_l1f, (unsigned)r, t);
            __syncthreads();
            {
                const float4* s = (const float4*)g_h2[(r + 1) & 1];
                float4* d = (float4*)(hS + 4096);
                #pragma unroll
                for (int i = 0; i < 4; ++i) d[t + i * 256] = ldcg4(s + t + i * 256);
            }
            __syncthreads();

            // phase B: U1 * h2[r-1]
            #pragma unroll
            for (int kk = 0; kk < 16; ++kk) {
                const int k = 512 + kg * 16 + kk;
                float4 w = w4[k * 9 + jg];
                const u64* hp = (const u64*)(hS + k * 8);
                u64 h0 = hp[0], h1 = hp[1], h2v = hp[2], h3 = hp[3];
                FMA16(w, h0, h1, h2v, h3)
            }

            #pragma unroll
            for (int i = 0; i < 16; ++i) {
                acc[i] = addp(acc[i], __shfl_xor_sync(0xffffffffu, acc[i], 8));
                acc[i] = addp(acc[i], __shfl_xor_sync(0xffffffffu, acc[i], 16));
            }
            if ((t & 24) == 0) {
                u64* rb = (u64*)(redS + ((t >> 5) * 8 + jg) * 34);
                #pragma unroll
                for (int i = 0; i < 16; ++i) rb[i] = acc[i];
            }
            __syncthreads();

            if (t < 64) {
                float s4[4];
                #pragma unroll
                for (int g = 0; g < 4; ++g) {
                    const int row = g * 8 + uu;
                    const int jgg = row >> 2, rrg = row & 3;
                    float s = biasv[g];
                    #pragma unroll
                    for (int k2 = 0; k2 < 8; ++k2)
                        s += redS[(k2 * 8 + jgg) * 34 + rrg * 8 + ub];
                    s4[g] = s;
                }
                float si = __fdividef(1.f, 1.f + __expf(-s4[0]));
                float sf = __fdividef(1.f, 1.f + __expf(-s4[1]));
                float tg = tanhf(s4[2]);
                float so = __fdividef(1.f, 1.f + __expf(-s4[3]));
                c_state = sf * c_state + si * tg;
                float h = so * fmaxf(c_state, 0.f);
                const int j = ubase + uu;
                __stcg(&g_h2[r & 1][j * 8 + ub], h);
                out[((size_t)(ub * TT + r)) * HH + j] = h;   // h2 sequence
                if (r == TT - 1) {
                    out[8388608 + 4096 + ub * 512 + j] = h;        // hh[1]
                    out[8396800 + 4096 + ub * 512 + j] = c_state;  // cc[1]
                }
            }
            __syncthreads();
            if (t == 0) strel(&g_l1f[lcta], (unsigned)(r + 1));
        }
    }
}

extern "C" void kernel_launch(void* const* d_in, const int* in_sizes, int n_in,
                              void* d_out, int out_size)
{
    const float* x    = (const float*)d_in[0];
    const float* w0_w = (const float*)d_in[1];
    const float* w0_b = (const float*)d_in[2];
    const float* u0_w = (const float*)d_in[3];
    const float* u0_b = (const float*)d_in[4];
    const float* w1_w = (const float*)d_in[5];
    const float* w1_b = (const float*)d_in[6];
    const float* u1_w = (const float*)d_in[7];
    const float* u1_b = (const float*)d_in[8];
    float* out = (float*)d_out;

    static int attr_done = 0;
    if (!attr_done) {
        cudaFuncSetAttribute(lstm_persist, cudaFuncAttributeMaxDynamicSharedMemorySize, SMEM_BYTES);
        attr_done = 1;
    }

    init_k<<<1, 256>>>();
    lstm_persist<<<NCTA, 256, SMEM_BYTES>>>(x, w0_w, w0_b, u0_w, u0_b,
                                            w1_w, w1_b, u1_w, u1_b, out);
}

// round 6
// speedup vs baseline: 1.0078x; 1.0078x over previous
#include <cuda_runtime.h>
#include <math.h>

// Problem constants
#define BB 8
#define TT 2048
#define DIN 256
#define HH 512
#define NCTA 128
#define L0N 64
#define NT 512

typedef unsigned long long u64;

// ---------------- device scratch ----------------
__device__ float g_h1buf[TT + 1][HH * BB];   // full h1 history, [j*8+b]
__device__ float g_h2[2][HH * BB];           // ping-pong h2
__device__ unsigned g_l0f[64];
__device__ unsigned g_l1f[64];

// ---------------- shared memory (floats) ----------------
// wS   : [1024][36]  = 36864
// hS   : [1024][8]   = 8192
// xS   : [256][10]   = 2560
// redS : [128][34]   = 4352
// gateS: [256]       = 256
#define OFF_H    36864
#define OFF_X    45056
#define OFF_RED  47616
#define OFF_GATE 51968
#define SMEM_FLOATS 52224
#define SMEM_BYTES (SMEM_FLOATS * 4)   // 208896 < 227KB

__device__ __forceinline__ u64 pk2(float x) {
    u64 r; asm("mov.b64 %0, {%1, %1};" : "=l"(r) : "f"(x)); return r;
}
__device__ __forceinline__ void fma2(u64& a, u64 b, u64 c) {
    asm("fma.rn.f32x2 %0, %1, %2, %0;" : "+l"(a) : "l"(b), "l"(c));
}
__device__ __forceinline__ u64 addp(u64 a, u64 b) {
    u64 r; asm("add.rn.f32x2 %0, %1, %2;" : "=l"(r) : "l"(a), "l"(b)); return r;
}
__device__ __forceinline__ float4 ldcg4(const float4* p) { return __ldcg(p); }
__device__ __forceinline__ unsigned ldacq(const unsigned* p) {
    unsigned v;
    asm volatile("ld.acquire.gpu.global.u32 %0, [%1];" : "=r"(v) : "l"(p) : "memory");
    return v;
}
__device__ __forceinline__ void strel(unsigned* p, unsigned v) {
    asm volatile("st.release.gpu.global.u32 [%0], %1;" :: "l"(p), "r"(v) : "memory");
}

__device__ __forceinline__ void poll64(const unsigned* f, unsigned tgt, int lane) {
    for (;;) {
        unsigned a = ldacq(f + lane);
        unsigned b = ldacq(f + 32 + lane);
        if (__all_sync(0xffffffffu, (a >= tgt) && (b >= tgt))) return;
    }
}

__device__ __forceinline__ float fast_sig(float x) {
    return __fdividef(1.f, 1.f + __expf(-x));
}
__device__ __forceinline__ float fast_tanh(float x) {
    float e = __expf(2.f * x);
    return 1.f - __fdividef(2.f, e + 1.f);
}

#define FMA16(W, H0, H1, H2, H3)                                        \
    { u64 wp;                                                           \
      wp = pk2(W.x); fma2(acc[0],wp,H0);  fma2(acc[1],wp,H1);           \
                     fma2(acc[2],wp,H2);  fma2(acc[3],wp,H3);           \
      wp = pk2(W.y); fma2(acc[4],wp,H0);  fma2(acc[5],wp,H1);           \
                     fma2(acc[6],wp,H2);  fma2(acc[7],wp,H3);           \
      wp = pk2(W.z); fma2(acc[8],wp,H0);  fma2(acc[9],wp,H1);           \
                     fma2(acc[10],wp,H2); fma2(acc[11],wp,H3);          \
      wp = pk2(W.w); fma2(acc[12],wp,H0); fma2(acc[13],wp,H1);          \
                     fma2(acc[14],wp,H2); fma2(acc[15],wp,H3); }

__global__ void init_k() {
    int t = threadIdx.x;
    for (int i = t; i < HH * BB; i += 256) g_h1buf[0][i] = 0.f;
    float* h2f = (float*)g_h2;
    for (int i = t; i < 2 * HH * BB; i += 256) h2f[i] = 0.f;
    if (t < 64) { g_l0f[t] = 0u; g_l1f[t] = 0u; }
}

__global__ void __launch_bounds__(NT, 1)
lstm_persist(const float* __restrict__ x,
             const float* __restrict__ w0w, const float* __restrict__ w0b,
             const float* __restrict__ u0w, const float* __restrict__ u0b,
             const float* __restrict__ w1w, const float* __restrict__ w1b,
             const float* __restrict__ u1w, const float* __restrict__ u1b,
             float* __restrict__ out)
{
    extern __shared__ float sm[];
    float* wS    = sm;
    float* hS    = sm + OFF_H;
    float* xS    = sm + OFF_X;
    float* redS  = sm + OFF_RED;
    float* gateS = sm + OFF_GATE;

    const int t   = threadIdx.x;
    const int cta = blockIdx.x;
    const int jg  = t & 7;       // row-group (4 rows)
    const int kg  = t >> 3;      // k-group 0..63
    const float4* w4 = (const float4*)wS;

    // update-phase roles (t < 256)
    const int urow  = t >> 3;    // row 0..31
    const int ubat  = t & 7;
    const int ugate = urow >> 3; // 0..3

    if (cta < L0N) {
        // ================= LAYER 0 =================
        const int ubase = cta * 8;
        for (int rr = 0; rr < 32; ++rr) {
            int g = (rr >> 3) * 512 + ubase + (rr & 7);
            for (int k = t; k < 768; k += NT)
                wS[k * 36 + rr] = (k < 512) ? u0w[g * 512 + k]
                                            : w0w[g * 256 + (k - 512)];
        }
        float biasv = 0.f;
        if (t < 256) {
            int gi = ugate * 512 + ubase + (urow & 7);
            biasv = w0b[gi] + u0b[gi];
        }
        __syncthreads();

        // x prefetch: one float4 per thread (b = t&7, d4 = t>>3)
        const int xb = t & 7, xd = t >> 3;
        const float* xrow = &x[(size_t)xb * TT * DIN];
        float4 xr = *(const float4*)&xrow[xd * 4];

        float c_state = 0.f;
        for (int r = 0; r < TT; ++r) {
            { float* p = &xS[(xd * 4) * 10 + xb];
              p[0] = xr.x; p[10] = xr.y; p[20] = xr.z; p[30] = xr.w; }
            if (r + 1 < TT) xr = *(const float4*)&xrow[(r + 1) * DIN + xd * 4];
            __syncthreads();

            u64 acc[16];
            #pragma unroll
            for (int i = 0; i < 16; ++i) acc[i] = 0ull;

            // phase A: W0 * x[r] (off-path)
            #pragma unroll
            for (int kk = 0; kk < 4; ++kk) {
                const int kx = kg * 4 + kk;
                float4 w = w4[(512 + kx) * 9 + jg];
                const u64* xp = (const u64*)(xS + kx * 10);
                u64 h0 = xp[0], h1 = xp[1], h2v = xp[2], h3 = xp[3];
                FMA16(w, h0, h1, h2v, h3)
            }

            if (t < 32) poll64(g_l0f, (unsigned)r, t);
            __syncthreads();
            {
                const float4* s = (const float4*)g_h1buf[r];
                float4* d = (float4*)hS;
                d[t] = ldcg4(s + t);
                d[t + 512] = ldcg4(s + t + 512);
            }
            __syncthreads();

            // phase B: U0 * h1[r]
            #pragma unroll
            for (int kk = 0; kk < 8; ++kk) {
                const int k = kg * 8 + kk;
                float4 w = w4[k * 9 + jg];
                const u64* hp = (const u64*)(hS + k * 8);
                u64 h0 = hp[0], h1 = hp[1], h2v = hp[2], h3 = hp[3];
                FMA16(w, h0, h1, h2v, h3)
            }

            #pragma unroll
            for (int i = 0; i < 16; ++i) {
                acc[i] = addp(acc[i], __shfl_xor_sync(0xffffffffu, acc[i], 8));
                acc[i] = addp(acc[i], __shfl_xor_sync(0xffffffffu, acc[i], 16));
            }
            if ((t & 24) == 0) {
                u64* rb = (u64*)(redS + ((t >> 5) * 8 + jg) * 34);
                #pragma unroll
                for (int i = 0; i < 16; ++i) rb[i] = acc[i];
            }
            __syncthreads();

            if (t < 256) {
                float s = biasv;
                #pragma unroll
                for (int w2 = 0; w2 < 16; ++w2)
                    s += redS[(w2 * 8 + (urow >> 2)) * 34 + (urow & 3) * 8 + ubat];
                gateS[urow * 8 + ubat] = (ugate == 2) ? fast_tanh(s) : fast_sig(s);
            }
            __syncthreads();

            if (t < 64) {
                const int uu = t >> 3, ub = t & 7;
                float ai = gateS[(0 * 8 + uu) * 8 + ub];
                float af = gateS[(1 * 8 + uu) * 8 + ub];
                float ag = gateS[(2 * 8 + uu) * 8 + ub];
                float ao = gateS[(3 * 8 + uu) * 8 + ub];
                c_state = af * c_state + ai * ag;
                float h = ao * fmaxf(c_state, 0.f);
                const int j = ubase + uu;
                __stcg(&g_h1buf[r + 1][j * 8 + ub], h);
                if (r == TT - 1) {
                    out[8388608 + ub * 512 + j] = h;        // hh[0]
                    out[8396800 + ub * 512 + j] = c_state;  // cc[0]
                }
            }
            __syncthreads();
            if (t == 0) strel(&g_l0f[cta], (unsigned)(r + 1));
        }
    } else {
        // ================= LAYER 1 =================
        const int lcta  = cta - L0N;
        const int ubase = lcta * 8;
        for (int rr = 0; rr < 32; ++rr) {
            int g = (rr >> 3) * 512 + ubase + (rr & 7);
            for (int k = t; k < 1024; k += NT)
                wS[k * 36 + rr] = (k < 512) ? w1w[g * 512 + k]
                                            : u1w[g * 512 + (k - 512)];
        }
        float biasv = 0.f;
        if (t < 256) {
            int gi = ugate * 512 + ubase + (urow & 7);
            biasv = w1b[gi] + u1b[gi];
        }
        __syncthreads();

        float c_state = 0.f;
        for (int r = 0; r < TT; ++r) {
            if (t < 32) poll64(g_l0f, (unsigned)(r + 1), t);
            __syncthreads();
            {
                const float4* s = (const float4*)g_h1buf[r + 1];
                float4* d = (float4*)hS;
                d[t] = ldcg4(s + t);
                d[t + 512] = ldcg4(s + t + 512);
            }
            __syncthreads();

            u64 acc[16];
            #pragma unroll
            for (int i = 0; i < 16; ++i) acc[i] = 0ull;

            // phase A: W1 * h1[r] (off-path)
            #pragma unroll
            for (int kk = 0; kk < 8; ++kk) {
                const int k = kg * 8 + kk;
                float4 w = w4[k * 9 + jg];
                const u64* hp = (const u64*)(hS + k * 8);
                u64 h0 = hp[0], h1 = hp[1], h2v = hp[2], h3 = hp[3];
                FMA16(w, h0, h1, h2v, h3)
            }

            if (t < 32) poll64(g_l1f, (unsigned)r, t);
            __syncthreads();
            {
                const float4* s = (const float4*)g_h2[(r + 1) & 1];
                float4* d = (float4*)(hS + 4096);
                d[t] = ldcg4(s + t);
                d[t + 512] = ldcg4(s + t + 512);
            }
            __syncthreads();

            // phase B: U1 * h2[r-1]
            #pragma unroll
            for (int kk = 0; kk < 8; ++kk) {
                const int k = 512 + kg * 8 + kk;
                float4 w = w4[k * 9 + jg];
                const u64* hp = (const u64*)(hS + k * 8);
                u64 h0 = hp[0], h1 = hp[1], h2v = hp[2], h3 = hp[3];
                FMA16(w, h0, h1, h2v, h3)
            }

            #pragma unroll
            for (int i = 0; i < 16; ++i) {
                acc[i] = addp(acc[i], __shfl_xor_sync(0xffffffffu, acc[i], 8));
                acc[i] = addp(acc[i], __shfl_xor_sync(0xffffffffu, acc[i], 16));
            }
            if ((t & 24) == 0) {
                u64* rb = (u64*)(redS + ((t >> 5) * 8 + jg) * 34);
                #pragma unroll
                for (int i = 0; i < 16; ++i) rb[i] = acc[i];
            }
            __syncthreads();

            if (t < 256) {
                float s = biasv;
                #pragma unroll
                for (int w2 = 0; w2 < 16; ++w2)
                    s += redS[(w2 * 8 + (urow >> 2)) * 34 + (urow & 3) * 8 + ubat];
                gateS[urow * 8 + ubat] = (ugate == 2) ? fast_tanh(s) : fast_sig(s);
            }
            __syncthreads();

            if (t < 64) {
                const int uu = t >> 3, ub = t & 7;
                float ai = gateS[(0 * 8 + uu) * 8 + ub];
                float af = gateS[(1 * 8 + uu) * 8 + ub];
                float ag = gateS[(2 * 8 + uu) * 8 + ub];
                float ao = gateS[(3 * 8 + uu) * 8 + ub];
                c_state = af * c_state + ai * ag;
                float h = ao * fmaxf(c_state, 0.f);
                const int j = ubase + uu;
                __stcg(&g_h2[r & 1][j * 8 + ub], h);
                out[((size_t)(ub * TT + r)) * HH + j] = h;   // h2 sequence
                if (r == TT - 1) {
                    out[8388608 + 4096 + ub * 512 + j] = h;        // hh[1]
                    out[8396800 + 4096 + ub * 512 + j] = c_state;  // cc[1]
                }
            }
            __syncthreads();
            if (t == 0) strel(&g_l1f[lcta], (unsigned)(r + 1));
        }
    }
}

extern "C" void kernel_launch(void* const* d_in, const int* in_sizes, int n_in,
                              void* d_out, int out_size)
{
    const float* x    = (const float*)d_in[0];
    const float* w0_w = (const float*)d_in[1];
    const float* w0_b = (const float*)d_in[2];
    const float* u0_w = (const float*)d_in[3];
    const float* u0_b = (const float*)d_in[4];
    const float* w1_w = (const float*)d_in[5];
    const float* w1_b = (const float*)d_in[6];
    const float* u1_w = (const float*)d_in[7];
    const float* u1_b = (const float*)d_in[8];
    float* out = (float*)d_out;

    static int attr_done = 0;
    if (!attr_done) {
        cudaFuncSetAttribute(lstm_persist, cudaFuncAttributeMaxDynamicSharedMemorySize, SMEM_BYTES);
        attr_done = 1;
    }

    init_k<<<1, 256>>>();
    lstm_persist<<<NCTA, NT, SMEM_BYTES>>>(x, w0_w, w0_b, u0_w, u0_b,
                                           w1_w, w1_b, u1_w, u1_b, out);
}